// round 12
// baseline (speedup 1.0000x reference)
#include <cuda_runtime.h>
#include <cuda_bf16.h>
#include <cuda_fp16.h>

// fp16 table + 8-lanes-per-row: one warp LDG.128 gathers 4 complete rows.
// Block 64 = 2 warps = 8 item-slots x 8 lanes; each lane owns 8 dims.

#define MAX_TABLE (100000 * 64)

__device__ __half g_table[MAX_TABLE];

__global__ __launch_bounds__(256)
void convert_kernel(const float4* __restrict__ src, int n4) {
    const int i = blockIdx.x * blockDim.x + threadIdx.x;
    if (i >= n4) return;
    const float4 f = __ldg(&src[i]);
    __half2* dst = reinterpret_cast<__half2*>(g_table) + (size_t)i * 2;
    dst[0] = __floats2half2_rn(f.x, f.y);
    dst[1] = __floats2half2_rn(f.z, f.w);
}

__device__ __forceinline__ void acc8(float4& lo, float4& hi, const uint4 g) {
    const float2 p0 = __half22float2(*reinterpret_cast<const __half2*>(&g.x));
    const float2 p1 = __half22float2(*reinterpret_cast<const __half2*>(&g.y));
    const float2 p2 = __half22float2(*reinterpret_cast<const __half2*>(&g.z));
    const float2 p3 = __half22float2(*reinterpret_cast<const __half2*>(&g.w));
    lo.x += p0.x; lo.y += p0.y; lo.z += p1.x; lo.w += p1.y;
    hi.x += p2.x; hi.y += p2.y; hi.z += p3.x; hi.w += p3.y;
}

__global__ __launch_bounds__(64)
void svdpp_kernel(const int* __restrict__ user_ids,
                  const int* __restrict__ item_ids,
                  const int* __restrict__ offsets,
                  const int* __restrict__ flat_implicit,
                  const float4* __restrict__ user_emb4,
                  const float4* __restrict__ item_emb4,
                  const float* __restrict__ user_bias,
                  const float* __restrict__ item_bias,
                  const float* __restrict__ global_bias,
                  float* __restrict__ out,
                  int B, int N) {
    const int b     = blockIdx.x;
    const int tid   = threadIdx.x;
    const int lane8 = tid & 7;          // 16B chunk within 128B fp16 row
    const int slot  = tid >> 3;         // item slot 0..7

    const int start = offsets[b];
    const int end   = (b + 1 < B) ? offsets[b + 1] : N;
    const int len   = end - start;

    const uint4* tab = reinterpret_cast<const uint4*>(g_table);

    float4 lo = make_float4(0.f, 0.f, 0.f, 0.f);
    float4 hi = make_float4(0.f, 0.f, 0.f, 0.f);

    int j = start + slot;
    // Unroll x2: 2 independent row loads per thread; per warp-instruction,
    // 4 complete rows are fetched (one 128B sector each).
    for (; j + 8 < end; j += 16) {
        const int i0 = __ldg(&flat_implicit[j]);
        const int i1 = __ldg(&flat_implicit[j + 8]);
        const uint4 g0 = tab[(size_t)i0 * 8 + lane8];
        const uint4 g1 = tab[(size_t)i1 * 8 + lane8];
        acc8(lo, hi, g0);
        acc8(lo, hi, g1);
    }
    if (j < end) {
        const uint4 g = tab[(size_t)__ldg(&flat_implicit[j]) * 8 + lane8];
        acc8(lo, hi, g);
    }

    // Combine the 4 slots within each warp (lanes fold onto lanes 0-7).
    #pragma unroll
    for (int m = 8; m <= 16; m <<= 1) {
        lo.x += __shfl_xor_sync(0xffffffffu, lo.x, m);
        lo.y += __shfl_xor_sync(0xffffffffu, lo.y, m);
        lo.z += __shfl_xor_sync(0xffffffffu, lo.z, m);
        lo.w += __shfl_xor_sync(0xffffffffu, lo.w, m);
        hi.x += __shfl_xor_sync(0xffffffffu, hi.x, m);
        hi.y += __shfl_xor_sync(0xffffffffu, hi.y, m);
        hi.z += __shfl_xor_sync(0xffffffffu, hi.z, m);
        hi.w += __shfl_xor_sync(0xffffffffu, hi.w, m);
    }

    // Cross-warp combine: warp 1 lanes 0-7 publish 8x {lo,hi}.
    __shared__ float4 s[8][2];
    if (tid >= 32 && tid < 40) { s[lane8][0] = lo; s[lane8][1] = hi; }
    __syncthreads();

    if (tid < 8) {
        const float4 olo = s[tid][0];
        const float4 ohi = s[tid][1];
        lo.x += olo.x; lo.y += olo.y; lo.z += olo.z; lo.w += olo.w;
        hi.x += ohi.x; hi.y += ohi.y; hi.z += ohi.z; hi.w += ohi.w;

        const float invnorm = (len > 0) ? rsqrtf((float)len) : 1.0f;
        const int u  = user_ids[b];
        const int it = item_ids[b];

        // Lane t owns dims 8t..8t+7 -> float4 rows 2t and 2t+1.
        const float4 ua = __ldg(&user_emb4[(size_t)u * 16 + 2 * tid]);
        const float4 ub4 = __ldg(&user_emb4[(size_t)u * 16 + 2 * tid + 1]);
        const float4 ia = __ldg(&item_emb4[(size_t)it * 16 + 2 * tid]);
        const float4 ib4 = __ldg(&item_emb4[(size_t)it * 16 + 2 * tid + 1]);

        float dot = (ua.x + lo.x * invnorm) * ia.x
                  + (ua.y + lo.y * invnorm) * ia.y
                  + (ua.z + lo.z * invnorm) * ia.z
                  + (ua.w + lo.w * invnorm) * ia.w
                  + (ub4.x + hi.x * invnorm) * ib4.x
                  + (ub4.y + hi.y * invnorm) * ib4.y
                  + (ub4.z + hi.z * invnorm) * ib4.z
                  + (ub4.w + hi.w * invnorm) * ib4.w;

        #pragma unroll
        for (int off = 4; off > 0; off >>= 1)
            dot += __shfl_down_sync(0x000000ffu, dot, off);

        if (tid == 0)
            out[b] = dot + user_bias[u] + item_bias[it] + global_bias[0];
    }
}

extern "C" void kernel_launch(void* const* d_in, const int* in_sizes, int n_in,
                              void* d_out, int out_size) {
    const int*    user_ids      = (const int*)d_in[0];
    const int*    item_ids      = (const int*)d_in[1];
    const int*    offsets       = (const int*)d_in[2];
    const int*    flat_implicit = (const int*)d_in[3];
    const float4* user_emb4     = (const float4*)d_in[4];
    const float4* item_emb4     = (const float4*)d_in[5];
    const float4* imp_emb4      = (const float4*)d_in[6];
    const float*  user_bias     = (const float*)d_in[7];
    const float*  item_bias     = (const float*)d_in[8];
    const float*  global_bias   = (const float*)d_in[9];
    float*        out           = (float*)d_out;

    const int B  = in_sizes[0];         // 16384
    const int N  = in_sizes[3];         // 819200
    const int n4 = in_sizes[6] / 4;     // fp32 table elems / 4

    convert_kernel<<<(n4 + 255) / 256, 256>>>(imp_emb4, n4);

    svdpp_kernel<<<B, 64>>>(user_ids, item_ids, offsets, flat_implicit,
                            user_emb4, item_emb4,
                            user_bias, item_bias, global_bias,
                            out, B, N);
}

// round 13
// speedup vs baseline: 1.1227x; 1.1227x over previous
#include <cuda_runtime.h>
#include <cuda_pipeline_primitives.h>

// cp.async double-buffered gather: CTA per row, 64 thr = 4 slots x 16 lanes.
// Tile = 16 items staged L2->smem via cp.async; each thread consumes exactly
// the chunks it staged -> no __syncthreads in the main loop.

#define TILE 16

__global__ __launch_bounds__(64)
void svdpp_kernel(const int* __restrict__ user_ids,
                  const int* __restrict__ item_ids,
                  const int* __restrict__ offsets,
                  const int* __restrict__ flat_implicit,
                  const float4* __restrict__ user_emb4,
                  const float4* __restrict__ item_emb4,
                  const float* __restrict__ imp_emb,
                  const float* __restrict__ user_bias,
                  const float* __restrict__ item_bias,
                  const float* __restrict__ global_bias,
                  float* __restrict__ out,
                  int B, int N) {
    const int b    = blockIdx.x;
    const int tid  = threadIdx.x;
    const int lane = tid & 15;          // float4 chunk within 64-float row
    const int slot = tid >> 4;          // 0..3

    const int start = offsets[b];
    const int end   = (b + 1 < B) ? offsets[b + 1] : N;
    const int len   = end - start;

    // Epilogue operands issued up front; latency hides under the gather.
    const int u  = __ldg(&user_ids[b]);
    const int it = __ldg(&item_ids[b]);
    const float4 u4 = __ldg(&user_emb4[(size_t)u * 16 + lane]);
    const float4 i4 = __ldg(&item_emb4[(size_t)it * 16 + lane]);
    const float  ub = __ldg(&user_bias[u]);
    const float  ib = __ldg(&item_bias[it]);
    const float  gb = __ldg(&global_bias[0]);

    // Double-buffered staging: [buf][row][64 floats + 4 pad].
    __shared__ __align__(16) float sbuf[2][TILE][68];

    const int T = (len + TILE - 1) / TILE;

    float4 acc = make_float4(0.f, 0.f, 0.f, 0.f);

    // --- stage tile k: thread stages chunk `lane` of rows slot+4i ---
    #define STAGE(k)                                                          \
    do {                                                                      \
        const int _base = start + (k) * TILE;                                 \
        const int _vr   = end - _base; /* valid rows (may exceed TILE) */     \
        _Pragma("unroll")                                                     \
        for (int _i = 0; _i < 4; ++_i) {                                      \
            const int _r = slot + 4 * _i;                                     \
            if (_r < _vr && _r < TILE) {                                      \
                const int _idx = __ldg(&flat_implicit[_base + _r]);           \
                __pipeline_memcpy_async(&sbuf[(k) & 1][_r][lane * 4],         \
                    imp_emb + (size_t)_idx * 64 + lane * 4, 16);              \
            }                                                                 \
        }                                                                     \
    } while (0)

    if (T > 0) { STAGE(0); __pipeline_commit(); }

    for (int k = 0; k < T; ++k) {
        const bool more = (k + 1 < T);
        if (more) { STAGE(k + 1); __pipeline_commit(); }
        if (more) __pipeline_wait_prior(1); else __pipeline_wait_prior(0);

        const int vr = end - (start + k * TILE);
        #pragma unroll
        for (int i = 0; i < 4; ++i) {
            const int r = slot + 4 * i;
            if (r < vr && r < TILE) {
                const float4 a = *reinterpret_cast<const float4*>(&sbuf[k & 1][r][lane * 4]);
                acc.x += a.x; acc.y += a.y; acc.z += a.z; acc.w += a.w;
            }
        }
    }
    #undef STAGE

    // Combine slots 0/1 (warp 0) and 2/3 (warp 1).
    acc.x += __shfl_xor_sync(0xffffffffu, acc.x, 16);
    acc.y += __shfl_xor_sync(0xffffffffu, acc.y, 16);
    acc.z += __shfl_xor_sync(0xffffffffu, acc.z, 16);
    acc.w += __shfl_xor_sync(0xffffffffu, acc.w, 16);

    __shared__ float4 s[16];
    if (tid >= 32 && tid < 48) s[lane] = acc;   // warp 1, lanes 0-15
    __syncthreads();

    if (tid < 16) {
        const float4 o = s[tid];
        acc.x += o.x; acc.y += o.y; acc.z += o.z; acc.w += o.w;

        const float invnorm = (len > 0) ? rsqrtf((float)len) : 1.0f;

        float dot = (u4.x + acc.x * invnorm) * i4.x
                  + (u4.y + acc.y * invnorm) * i4.y
                  + (u4.z + acc.z * invnorm) * i4.z
                  + (u4.w + acc.w * invnorm) * i4.w;

        #pragma unroll
        for (int off = 8; off > 0; off >>= 1)
            dot += __shfl_down_sync(0x0000ffffu, dot, off);

        if (tid == 0)
            out[b] = dot + ub + ib + gb;
    }
}

extern "C" void kernel_launch(void* const* d_in, const int* in_sizes, int n_in,
                              void* d_out, int out_size) {
    const int*    user_ids      = (const int*)d_in[0];
    const int*    item_ids      = (const int*)d_in[1];
    const int*    offsets       = (const int*)d_in[2];
    const int*    flat_implicit = (const int*)d_in[3];
    const float4* user_emb4     = (const float4*)d_in[4];
    const float4* item_emb4     = (const float4*)d_in[5];
    const float*  imp_emb       = (const float*)d_in[6];
    const float*  user_bias     = (const float*)d_in[7];
    const float*  item_bias     = (const float*)d_in[8];
    const float*  global_bias   = (const float*)d_in[9];
    float*        out           = (float*)d_out;

    const int B = in_sizes[0];          // 16384
    const int N = in_sizes[3];          // 819200

    svdpp_kernel<<<B, 64>>>(user_ids, item_ids, offsets, flat_implicit,
                            user_emb4, item_emb4, imp_emb,
                            user_bias, item_bias, global_bias,
                            out, B, N);
}